// round 16
// baseline (speedup 1.0000x reference)
#include <cuda_runtime.h>
#include <cuda_fp16.h>
#include <math.h>
#include <stdint.h>

#define NUM_NODES 262144
#define HID 256
#define NGRAPH 1024
#define NTILES (NUM_NODES / 128)   // 2048
#define NSM 148

// ---------------- scratch (static device globals) ----------------
__device__ float g_sw[NGRAPH];     // segment sum of exp(score)
// W1^T fp16 b-frags: [kstep 0..15][ntpair 0..7][lane 0..31][b0e,b1e,b0o,b1o]
__device__ uint32_t g_B[16 * 8 * 32 * 4];    // 16384 u32 = 64KB

__device__ __forceinline__ uint32_t smem_u32(const void* p) {
    uint32_t a;
    asm("{ .reg .u64 t; cvta.to.shared.u64 t, %1; cvt.u32.u64 %0, t; }" : "=r"(a) : "l"(p));
    return a;
}
__device__ __forceinline__ void mma_f16(float* c, const uint32_t* a,
                                        uint32_t b0, uint32_t b1) {
    asm volatile(
        "mma.sync.aligned.m16n8k16.row.col.f32.f16.f16.f32 "
        "{%0,%1,%2,%3}, {%4,%5,%6,%7}, {%8,%9}, {%0,%1,%2,%3};"
        : "+f"(c[0]), "+f"(c[1]), "+f"(c[2]), "+f"(c[3])
        : "r"(a[0]), "r"(a[1]), "r"(a[2]), "r"(a[3]), "r"(b0), "r"(b1));
}
__device__ __forceinline__ void ldsm_x4(uint32_t* a, uint32_t addr) {
    asm volatile("ldmatrix.sync.aligned.m8n8.x4.shared.b16 {%0,%1,%2,%3}, [%4];"
        : "=r"(a[0]), "=r"(a[1]), "=r"(a[2]), "=r"(a[3]) : "r"(addr));
}
__device__ __forceinline__ float tanh_fast(float h) {
    float t;
    asm("tanh.approx.f32 %0, %1;" : "=f"(t) : "f"(h));
    return t;
}

// ---------------- prep + init fused ----------------
// grid 1024 x 256. All threads zero out/g_sw; blocks 0..15 also build B frags.
__global__ void prep_kernel(const float* __restrict__ W1,
                            float* __restrict__ out) {
    int i = blockIdx.x * 256 + threadIdx.x;
    if (i < NGRAPH * HID) out[i] = 0.f;
    if (i < NGRAPH) g_sw[i] = 0.f;
    if (i >= 4096) return;
    int l = i & 31, ntp = (i >> 5) & 7, ks = i >> 8;   // ks 0..15
    int gr = l >> 2, qc = l & 3;
    int kp = ks * 8 + qc;
    uint32_t q[4];
    #pragma unroll
    for (int e = 0; e < 2; ++e) {
        int n = (2 * ntp + e) * 8 + gr;
        __half2 v0 = __floats2half2_rn(W1[(2 * kp) * 128 + n],
                                       W1[(2 * kp + 1) * 128 + n]);
        __half2 v1 = __floats2half2_rn(W1[(2 * (kp + 4)) * 128 + n],
                                       W1[(2 * (kp + 4) + 1) * 128 + n]);
        q[e * 2]     = *(uint32_t*)&v0;
        q[e * 2 + 1] = *(uint32_t*)&v1;
    }
    ((uint4*)g_B)[i] = make_uint4(q[0], q[1], q[2], q[3]);
}

// ---------------------------------------------------------------------------
// fused score+pool. Persistent per-tile A slab (16 rows x 256 fp16 cols),
// pool from SMEM. 2-chunk-deep ping-pong LDG prefetch (v/v2) doubles MLP.
// dyn smem u32: B quads [0, 16384) ; A slabs: warp w at 16384 + w*2112
// (16 rows x 132 u32 pitch; chunk c at col c*32).
// ---------------------------------------------------------------------------
#define A_OFF 16384
#define A_SLAB 2112
#define A_PITCH 132

// store 8 float4 regs (chunk data) as fp16 into slab chunk col
#define STORE_CHUNK(buf, cc) do { \
    _Pragma("unroll") \
    for (int i = 0; i < 8; ++i) { \
        int f = i * 32 + l; \
        int r = f >> 4, q = f & 15; \
        __half2 h01 = __floats2half2_rn((buf)[i].x, (buf)[i].y); \
        __half2 h23 = __floats2half2_rn((buf)[i].z, (buf)[i].w); \
        uint64_t hv = (uint64_t)(*(uint32_t*)&h01) \
                    | ((uint64_t)(*(uint32_t*)&h23) << 32); \
        *(uint64_t*)(Ah + r * A_PITCH + (cc) * 32 + q * 2) = hv; \
    } } while (0)

#define LOAD_CHUNK(buf, rb, cc) do { \
    _Pragma("unroll") \
    for (int i = 0; i < 8; ++i) { \
        int f = i * 32 + l; \
        (buf)[i] = xg[(size_t)((rb) + (f >> 4)) * 64 + (cc) * 16 + (f & 15)]; \
    } } while (0)

#define MMA_CHUNK(cc) do { \
    _Pragma("unroll") \
    for (int k16 = 0; k16 < 4; ++k16) { \
        uint32_t a[4]; \
        ldsm_x4(a, a_base + (cc) * 128 + k16 * 32); \
        const uint4* Bk = Bq + (((cc) * 4 + k16) * 8) * 32 + l; \
        _Pragma("unroll") \
        for (int ntp = 0; ntp < 8; ++ntp) { \
            uint4 q = Bk[ntp * 32]; \
            mma_f16(acc[2 * ntp],     a, q.x, q.y); \
            mma_f16(acc[2 * ntp + 1], a, q.z, q.w); \
        } \
    } } while (0)

__global__ void __launch_bounds__(256, 1) score_kernel(
    const float* __restrict__ x,
    const int* __restrict__ batch,
    const float* __restrict__ b1,
    const float* __restrict__ W2,
    const float* __restrict__ b2,
    float* __restrict__ out)
{
    extern __shared__ uint32_t sm[];
    __shared__ float sb1[128], sW2[128];

    const int tid = threadIdx.x, w = tid >> 5, l = tid & 31;
    const int gr = l >> 2, qc = l & 3;

    {   // B copy: 16384 u32 = 4096 float4
        const float4* src = (const float4*)g_B;
        float4* dst = (float4*)sm;
        #pragma unroll
        for (int i = 0; i < 16; ++i) dst[tid + i * 256] = src[tid + i * 256];
    }
    if (tid < 128) { sb1[tid] = b1[tid]; sW2[tid] = W2[tid]; }
    __syncthreads();

    const float b2v = __ldg(&b2[0]);
    uint32_t* const Ah = sm + A_OFF + w * A_SLAB;
    const uint32_t a_base = smem_u32(Ah) + (l & 15) * (A_PITCH * 4) + (l >> 4) * 16;
    const uint4* const Bq = (const uint4*)sm;     // [kstep][ntp][lane]
    const float4* xg = (const float4*)x;          // [node][64]
    const int upool = (l >> 4) * 32 + 2 * (l & 15);   // pool LDS.64 col offset

    float4 v[8], v2[8];
    {   // preload chunks 0,1 of first tile
        const int rb0 = blockIdx.x * 128 + w * 16;
        LOAD_CHUNK(v, rb0, 0);
        LOAD_CHUNK(v2, rb0, 1);
    }

    for (int t = blockIdx.x; t < NTILES; t += NSM) {
        const int rbase = t * 128 + w * 16;
        const int rnext = (t + NSM) * 128 + w * 16;
        const bool more = (t + NSM) < NTILES;

        float acc[16][4];
        #pragma unroll
        for (int nt = 0; nt < 16; ++nt)
            #pragma unroll
            for (int j = 0; j < 4; ++j) acc[nt][j] = 0.f;

        // c = 0: store v(c0), load c2 -> v, mma c0
        STORE_CHUNK(v, 0);
        __syncwarp();
        LOAD_CHUNK(v, rbase, 2);
        MMA_CHUNK(0);
        // c = 1: store v2(c1), load c3 -> v2, mma c1
        STORE_CHUNK(v2, 1);
        __syncwarp();
        LOAD_CHUNK(v2, rbase, 3);
        MMA_CHUNK(1);
        // c = 2: store v(c2), load next-tile c0 -> v, mma c2
        STORE_CHUNK(v, 2);
        __syncwarp();
        if (more) LOAD_CHUNK(v, rnext, 0);
        MMA_CHUNK(2);
        // c = 3: store v2(c3), load next-tile c1 -> v2, mma c3
        STORE_CHUNK(v2, 3);
        __syncwarp();
        if (more) LOAD_CHUNK(v2, rnext, 1);
        MMA_CHUNK(3);

        // epilogue: row scores; quad xor-reduce leaves p0/p1 in all quad lanes
        float p0 = 0.f, p1 = 0.f;
        #pragma unroll
        for (int nt = 0; nt < 16; ++nt) {
            #pragma unroll
            for (int j = 0; j < 2; ++j) {
                int col = nt * 8 + qc * 2 + j;
                float bb = sb1[col], ww = sW2[col];
                p0 = fmaf(tanh_fast(acc[nt][j] + bb), ww, p0);
                p1 = fmaf(tanh_fast(acc[nt][2 + j] + bb), ww, p1);
            }
        }
        p0 += __shfl_xor_sync(0xFFFFFFFFu, p0, 1);
        p0 += __shfl_xor_sync(0xFFFFFFFFu, p0, 2);
        p1 += __shfl_xor_sync(0xFFFFFFFFu, p1, 1);
        p1 += __shfl_xor_sync(0xFFFFFFFFu, p1, 2);

        // ---- pool phase: read x (fp16) from the slab, no global traffic ----
        float4 accA = make_float4(0.f, 0.f, 0.f, 0.f);
        float4 accB = make_float4(0.f, 0.f, 0.f, 0.f);
        float wsum = 0.f;
        int curb = __ldg(&batch[rbase]);
        #pragma unroll
        for (int r = 0; r < 16; ++r) {
            float sc = (r < 8) ? __shfl_sync(0xFFFFFFFFu, p0, r * 4)
                               : __shfl_sync(0xFFFFFFFFu, p1, (r - 8) * 4);
            float wv = __expf(sc + b2v);
            int b = __ldg(&batch[rbase + r]);
            if (b != curb) {
                float* o = &out[curb * HID + l * 4];
                atomicAdd(o + 0, accA.x); atomicAdd(o + 1, accA.y);
                atomicAdd(o + 2, accA.z); atomicAdd(o + 3, accA.w);
                float* o2 = o + 128;
                atomicAdd(o2 + 0, accB.x); atomicAdd(o2 + 1, accB.y);
                atomicAdd(o2 + 2, accB.z); atomicAdd(o2 + 3, accB.w);
                if (l == 0) atomicAdd(&g_sw[curb], wsum);
                accA = make_float4(0.f, 0.f, 0.f, 0.f);
                accB = make_float4(0.f, 0.f, 0.f, 0.f);
                wsum = 0.f;
                curb = b;
            }
            wsum += wv;
            const uint32_t* row = Ah + r * A_PITCH;
            uint32_t pa0 = row[upool],      pa1 = row[upool + 1];
            uint32_t pb0 = row[64 + upool], pb1 = row[64 + upool + 1];
            float2 fa0 = __half22float2(*(__half2*)&pa0);
            float2 fa1 = __half22float2(*(__half2*)&pa1);
            float2 fb0 = __half22float2(*(__half2*)&pb0);
            float2 fb1 = __half22float2(*(__half2*)&pb1);
            accA.x = fmaf(fa0.x, wv, accA.x); accA.y = fmaf(fa0.y, wv, accA.y);
            accA.z = fmaf(fa1.x, wv, accA.z); accA.w = fmaf(fa1.y, wv, accA.w);
            accB.x = fmaf(fb0.x, wv, accB.x); accB.y = fmaf(fb0.y, wv, accB.y);
            accB.z = fmaf(fb1.x, wv, accB.z); accB.w = fmaf(fb1.y, wv, accB.w);
        }
        {
            float* o = &out[curb * HID + l * 4];
            atomicAdd(o + 0, accA.x); atomicAdd(o + 1, accA.y);
            atomicAdd(o + 2, accA.z); atomicAdd(o + 3, accA.w);
            float* o2 = o + 128;
            atomicAdd(o2 + 0, accB.x); atomicAdd(o2 + 1, accB.y);
            atomicAdd(o2 + 2, accB.z); atomicAdd(o2 + 3, accB.w);
            if (l == 0) atomicAdd(&g_sw[curb], wsum);
        }
    }
}

// ---------------- normalize: out[b][h] /= S[b] ----------------
__global__ void norm_kernel(float* __restrict__ out) {
    int i = blockIdx.x * blockDim.x + threadIdx.x;   // 0..262143
    float s = g_sw[i >> 8];
    float inv = (s > 0.f) ? __fdividef(1.f, s) : 0.f;
    out[i] *= inv;
}

extern "C" void kernel_launch(void* const* d_in, const int* in_sizes, int n_in,
                              void* d_out, int out_size) {
    const float* x     = (const float*)d_in[0];
    const int*   batch = (const int*)d_in[1];
    const float* W1    = (const float*)d_in[2];
    const float* b1    = (const float*)d_in[3];
    const float* W2    = (const float*)d_in[4];
    const float* b2    = (const float*)d_in[5];
    float* out = (float*)d_out;

    const int dyn = (A_OFF + 8 * A_SLAB) * 4;   // 65536 + 67584 = 133120 B
    cudaFuncSetAttribute(score_kernel, cudaFuncAttributeMaxDynamicSharedMemorySize, dyn);

    prep_kernel<<<NGRAPH, 256>>>(W1, out);
    score_kernel<<<NSM, 256, dyn>>>(x, batch, b1, W2, b2, out);
    norm_kernel<<<NGRAPH * HID / 256, 256>>>(out);
}